// round 14
// baseline (speedup 1.0000x reference)
#include <cuda_runtime.h>
#include <cuda_bf16.h>
#include <cuda_fp16.h>
#include <cstdint>

#define NLAYERS 4
#define HID 512
#define BATCH 32
#define SEQ 2048
#define MTOT (BATCH*SEQ)          // 65536
#define NC 128                    // summary chunks
#define TC (SEQ/NC)               // 16 steps per summary chunk
#define LNC 64                    // scan_ln chunks
#define LTC (SEQ/LNC)             // 32 steps per scan_ln chunk
#define STEP 8                    // timesteps per reduction round in scan_ln
#define H2 (HID/2)                // 256 channel-pairs per row
#define H4 (HID/4)                // 128 channel-quads per row

// ---------------- GEMM tiling ----------------
#define BM 128
#define BN 128
#define BK 32
#define LDA 40                    // BK + 8 pad (row = 80B)
#define LDB 136                   // BN + 8 pad (row = 272B)
#define STAGE_EL (BM*LDA + BK*LDB)                // 9472 fp16
#define SMEM_BYTES (2*STAGE_EL*2)                 // 37888 bytes

// ---------------- scratch ----------------
__device__ __half g_ah[(size_t)MTOT * HID];       // a = sigmoid(-k)   (fp16)
__device__ __half g_gp[(size_t)MTOT * HID];       // gp = g(p)         (fp16)
__device__ __half g_Af[(size_t)MTOT * HID];       // activations / residual (fp16)
__device__ __half g_Wf[(size_t)NLAYERS * 2 * HID * HID];  // weights (fp16)
__device__ float g_cA[BATCH * NC * HID];
__device__ float g_cB[BATCH * NC * HID];
__device__ float g_hin[BATCH * NC * HID];

// ---------------- helpers ----------------
__device__ __forceinline__ uint32_t saddr(const void* p) {
    return (uint32_t)__cvta_generic_to_shared(p);
}
__device__ __forceinline__ void cpasync16(void* smem, const void* g) {
    asm volatile("cp.async.cg.shared.global [%0], [%1], 16;"
                 :: "r"(saddr(smem)), "l"(g));
}
__device__ __forceinline__ void cp_commit() {
    asm volatile("cp.async.commit_group;");
}
__device__ __forceinline__ void cp_wait0() {
    asm volatile("cp.async.wait_group 0;");
}
__device__ __forceinline__ void ldm_x4(uint32_t* r, uint32_t a) {
    asm volatile("ldmatrix.sync.aligned.m8n8.x4.shared.b16 {%0,%1,%2,%3}, [%4];"
                 : "=r"(r[0]), "=r"(r[1]), "=r"(r[2]), "=r"(r[3]) : "r"(a));
}
__device__ __forceinline__ void ldm_x2t(uint32_t* r, uint32_t a) {
    asm volatile("ldmatrix.sync.aligned.m8n8.x2.trans.shared.b16 {%0,%1}, [%2];"
                 : "=r"(r[0]), "=r"(r[1]) : "r"(a));
}
__device__ __forceinline__ void mma16816(float* c, const uint32_t* a, const uint32_t* b) {
    asm volatile(
        "mma.sync.aligned.m16n8k16.row.col.f32.f16.f16.f32 "
        "{%0,%1,%2,%3}, {%4,%5,%6,%7}, {%8,%9}, {%0,%1,%2,%3};"
        : "+f"(c[0]), "+f"(c[1]), "+f"(c[2]), "+f"(c[3])
        : "r"(a[0]), "r"(a[1]), "r"(a[2]), "r"(a[3]), "r"(b[0]), "r"(b[1]));
}
__device__ __forceinline__ float sig_neg(float v) {     // sigmoid(-v)
    return __fdividef(1.f, 1.f + __expf(v));
}
__device__ __forceinline__ float gfun(float v) {        // minGRU g()
    return (v >= 0.f) ? (v + 0.5f) : __fdividef(1.f, 1.f + __expf(-v));
}
__device__ __forceinline__ float4 half4_to_float4(uint2 v) {
    float2 lo = __half22float2(*(__half2*)&v.x);
    float2 hi = __half22float2(*(__half2*)&v.y);
    return make_float4(lo.x, lo.y, hi.x, hi.y);
}

// ============================================================================
// One-shot conversion kernels
// ============================================================================
__global__ void __launch_bounds__(256) conv_w(const float* __restrict__ Wz,
                                              const float* __restrict__ Wh) {
    size_t i = (size_t)blockIdx.x * 256 + threadIdx.x;    // over 4*512*512
    size_t l = i >> 18, r = i & ((1u << 18) - 1);
    g_Wf[((l * 2 + 0) << 18) + r] = __float2half_rn(Wz[i]);
    g_Wf[((l * 2 + 1) << 18) + r] = __float2half_rn(Wh[i]);
}

__global__ void __launch_bounds__(256) conv_x(const float* __restrict__ x) {
    size_t i = (size_t)blockIdx.x * 256 + threadIdx.x;    // over MTOT*HID/2
    float2 v = ((const float2*)x)[i];
    ((__half2*)g_Af)[i] = __floats2half2_rn(v.x, v.y);
}

// ============================================================================
// Fused dual GEMM, fp16 operands, fp32 accumulate.
// Epilogue applies the gate activation: zsel=0 stores a=sigmoid(-(k)),
// zsel=1 stores gp=g(p).  grid = (8, MTOT/128).
// ============================================================================
__global__ void __launch_bounds__(256, 2) gates_gemm(
    int layer, const float* __restrict__ bz, const float* __restrict__ bh)
{
    extern __shared__ __align__(16) char smem_raw[];
    __half* s = (__half*)smem_raw;

    const int tid  = threadIdx.x;
    const int lane = tid & 31;
    const int warp = tid >> 5;
    const int wm   = warp >> 2;
    const int wn   = warp & 3;
    const int zsel = blockIdx.x >> 2;
    const int colBase = (blockIdx.x & 3) * BN;
    const size_t rowBase = (size_t)blockIdx.y * BM;

    const __half* W_   = g_Wf + (((size_t)layer * 2 + zsel) << 18);
    const float* bias  = zsel ? bh : bz;
    __half*      Out   = zsel ? g_gp : g_ah;

    auto issue = [&](int kt, int st) {
        __half* sb = s + st * STAGE_EL;
        {   // A: 512 chunks of 16B (4 per row), 2 per thread
#pragma unroll
            for (int j = 0; j < 2; ++j) {
                int i = tid + 256 * j;
                int row = i >> 2, ch = i & 3;
                const __half* gsrc = g_Af + (rowBase + row) * HID + kt * BK + ch * 8;
                cpasync16(sb + row * LDA + ch * 8, gsrc);
            }
        }
        {   // B: 512 chunks of 16B (16 per row), 2 per thread
#pragma unroll
            for (int j = 0; j < 2; ++j) {
                int i = tid + 256 * j;
                int row = i >> 4, ch = i & 15;
                const __half* gsrc = W_ + (size_t)(kt * BK + row) * HID + colBase + ch * 8;
                cpasync16(sb + BM * LDA + row * LDB + ch * 8, gsrc);
            }
        }
        cp_commit();
    };

    float acc[4][4][4];
#pragma unroll
    for (int mt = 0; mt < 4; ++mt)
#pragma unroll
        for (int nt = 0; nt < 4; ++nt)
#pragma unroll
            for (int r = 0; r < 4; ++r) acc[mt][nt][r] = 0.f;

    auto comp = [&](int st) {
        const __half* sA = s + st * STAGE_EL;
        const __half* sB = sA + BM * LDA;
#pragma unroll
        for (int ks = 0; ks < 2; ++ks) {
            uint32_t B[4][2];
#pragma unroll
            for (int nt = 0; nt < 4; ++nt) {
                int br = ks * 16 + (lane & 15);
                int bc = wn * 32 + nt * 8;
                ldm_x2t(B[nt], saddr(sB + br * LDB + bc));
            }
#pragma unroll
            for (int mt = 0; mt < 4; ++mt) {
                uint32_t A[4];
                int ar = wm * 64 + mt * 16 + (lane & 15);
                int ac = ks * 16 + ((lane >> 4) << 3);
                ldm_x4(A, saddr(sA + ar * LDA + ac));
#pragma unroll
                for (int nt = 0; nt < 4; ++nt)
                    mma16816(acc[mt][nt], A, B[nt]);
            }
        }
    };

    issue(0, 0);
    const int KI = HID / BK;    // 16
    for (int kt = 0; kt < KI; ++kt) {
        int st = kt & 1;
        cp_wait0();
        __syncthreads();
        if (kt + 1 < KI) issue(kt + 1, st ^ 1);
        comp(st);
    }

#pragma unroll
    for (int mt = 0; mt < 4; ++mt) {
        size_t r0 = rowBase + wm * 64 + mt * 16 + (lane >> 2);
#pragma unroll
        for (int nt = 0; nt < 4; ++nt) {
            int cb = colBase + wn * 32 + nt * 8 + ((lane & 3) << 1);
            float2 bs = *(const float2*)(bias + cb);
            float v0 = acc[mt][nt][0] + bs.x, v1 = acc[mt][nt][1] + bs.y;
            float v2 = acc[mt][nt][2] + bs.x, v3 = acc[mt][nt][3] + bs.y;
            if (zsel == 0) {
                v0 = sig_neg(v0); v1 = sig_neg(v1);
                v2 = sig_neg(v2); v3 = sig_neg(v3);
            } else {
                v0 = gfun(v0); v1 = gfun(v1);
                v2 = gfun(v2); v3 = gfun(v3);
            }
            *(__half2*)(Out + r0 * HID + cb)       = __floats2half2_rn(v0, v1);
            *(__half2*)(Out + (r0 + 8) * HID + cb) = __floats2half2_rn(v2, v3);
        }
    }
}

// ============================================================================
// Scan summary pass: chunk (P, S); pure FMA (activations precomputed).
// grid = BATCH*NC = 4096 blocks x 128 threads, 4 channels/thread, TC=16 steps.
// ============================================================================
__global__ void __launch_bounds__(128) scan_summary() {
    int b     = blockIdx.x >> 7;                  // NC = 128
    int chunk = blockIdx.x & (NC - 1);
    int c4    = threadIdx.x;                      // quad index 0..127
    size_t base = ((size_t)(b * SEQ + chunk * TC)) * H4 + c4;

    const uint2* a4g = (const uint2*)g_ah;
    const uint2* g4g = (const uint2*)g_gp;

    float S[4] = {0.f, 0.f, 0.f, 0.f};
    float P[4] = {1.f, 1.f, 1.f, 1.f};
#pragma unroll
    for (int t = 0; t < TC; ++t) {
        size_t o = base + (size_t)t * H4;
        float4 a = half4_to_float4(__ldcs(a4g + o));
        float4 g = half4_to_float4(__ldcs(g4g + o));
        S[0] = fmaf(a.x, S[0] - g.x, g.x);  P[0] *= a.x;
        S[1] = fmaf(a.y, S[1] - g.y, g.y);  P[1] *= a.y;
        S[2] = fmaf(a.z, S[2] - g.z, g.z);  P[2] *= a.z;
        S[3] = fmaf(a.w, S[3] - g.w, g.w);  P[3] *= a.w;
    }
    ((float4*)g_cA)[(b * NC + chunk) * H4 + c4] = make_float4(P[0], P[1], P[2], P[3]);
    ((float4*)g_cB)[(b * NC + chunk) * H4 + c4] = make_float4(S[0], S[1], S[2], S[3]);
}

// ============================================================================
// Chain chunk summaries; emit per-chunk h_in and final hiddens.
// ============================================================================
__global__ void __launch_bounds__(256) scanB(const float* __restrict__ h0l,
                                             float* __restrict__ hid_out) {
    int idx = blockIdx.x * 256 + threadIdx.x;   // 16384
    int b = idx >> 9, c = idx & 511;
    float x0 = h0l[b * HID + c];
    float h = (x0 >= 0.f) ? (x0 + 0.5f)
                          : __fdividef(1.f, 1.f + __expf(-x0));
#pragma unroll 16
    for (int j = 0; j < NC; ++j) {
        g_hin[(b * NC + j) * HID + c] = h;
        h = fmaf(g_cA[(b * NC + j) * HID + c], h, g_cB[(b * NC + j) * HID + c]);
    }
    hid_out[b * HID + c] = h;
}

// ============================================================================
// Fused scan + LayerNorm + residual (pure-FMA recurrence).
// One block per (b, ln-chunk): 256 threads x 2 channels; LTC=32 steps in
// 4 pipelined STEP-rounds (the R12-proven shape). Chunk-entry h comes from
// summary boundary 2*chunk (NC=128 grid of boundaries).
// Residual source: fp32 x (layer 0) or fp16 g_Af in place (layers 1..3).
// Output: layers 0-2 write only fp16 g_Af; layer 3 writes only fp32 d_out.
// ============================================================================
__global__ void __launch_bounds__(256, 2) scan_ln(const float* __restrict__ residf,
                                                  const float* __restrict__ gamma,
                                                  const float* __restrict__ beta,
                                                  float* __restrict__ outp,
                                                  int resid_is_fp16,
                                                  int write_out,
                                                  int write_split) {
    __shared__ float red[8][16];      // [warp][8 x s, 8 x s2]
    __shared__ float bcast[2][STEP];  // [mu | rstd][step]
    int b = blockIdx.x >> 6, chunk = blockIdx.x & (LNC - 1);
    int c2 = threadIdx.x, lane = c2 & 31, warp = c2 >> 5;

    float2 h   = ((const float2*)g_hin)[(b * NC + chunk * 2) * H2 + c2];
    float2 gm  = __ldg((const float2*)gamma + c2);
    float2 bt  = __ldg((const float2*)beta + c2);
    size_t base2 = ((size_t)b * SEQ + chunk * LTC) * H2 + c2;   // pair index

    const __half2* a2g    = (const __half2*)g_ah;
    const __half2* gp2g   = (const __half2*)g_gp;
    const __half2* residh = (const __half2*)g_Af;   // device-side symbol address
    const float2*  r2g    = (const float2*)residf;
    float2*        o2g    = (float2*)outp;
    __half2*       af2g   = (__half2*)g_Af;

    __half2 ac[STEP], gc[STEP];
    float2  rc[STEP];
#pragma unroll
    for (int j = 0; j < STEP; ++j) {              // prologue loads (round 0)
        size_t o = base2 + (size_t)j * H2;
        ac[j] = __ldcs(a2g + o);
        gc[j] = __ldcs(gp2g + o);
        rc[j] = resid_is_fp16 ? __half22float2(__ldcs(residh + o))
                              : __ldcs(r2g + o);
    }

#pragma unroll
    for (int t0 = 0; t0 < LTC; t0 += STEP) {
        float2 h8[STEP];
        float s8[STEP], q8[STEP];
#pragma unroll
        for (int j = 0; j < STEP; ++j) {          // 8-step h chain (2 ch)
            float2 av = __half22float2(ac[j]);
            float2 gv = __half22float2(gc[j]);
            h.x = fmaf(av.x, h.x - gv.x, gv.x);
            h.y = fmaf(av.y, h.y - gv.y, gv.y);
            h8[j] = h;
            s8[j] = h.x + h.y;
            q8[j] = h.x * h.x + h.y * h.y;
        }
        float2 r8[STEP];
#pragma unroll
        for (int j = 0; j < STEP; ++j) r8[j] = rc[j];

        // prefetch next round while the reduction runs
        if (t0 + STEP < LTC) {
#pragma unroll
            for (int j = 0; j < STEP; ++j) {
                size_t o = base2 + (size_t)(t0 + STEP + j) * H2;
                ac[j] = __ldcs(a2g + o);
                gc[j] = __ldcs(gp2g + o);
                rc[j] = resid_is_fp16 ? __half22float2(__ldcs(residh + o))
                                      : __ldcs(r2g + o);
            }
        }

        // warp butterfly: 16 independent reductions, full ILP
#pragma unroll
        for (int off = 16; off; off >>= 1) {
#pragma unroll
            for (int j = 0; j < STEP; ++j) {
                s8[j] += __shfl_xor_sync(0xffffffffu, s8[j], off);
                q8[j] += __shfl_xor_sync(0xffffffffu, q8[j], off);
            }
        }
        if (lane == 0) {
#pragma unroll
            for (int j = 0; j < STEP; ++j) {
                red[warp][j]        = s8[j];
                red[warp][j + STEP] = q8[j];
            }
        }
        __syncthreads();
        if (warp == 0) {
            float v = 0.f;
            if (lane < 16) {
#pragma unroll
                for (int w = 0; w < 8; ++w) v += red[w][lane];
            }
            float vq = __shfl_down_sync(0xffffffffu, v, STEP);
            if (lane < STEP) {
                float mu  = v * (1.f / HID);
                float var = fmaf(vq, 1.f / HID, -mu * mu);
                bcast[0][lane] = mu;
                bcast[1][lane] = rsqrtf(var + 1e-5f);
            }
        }
        __syncthreads();
#pragma unroll
        for (int j = 0; j < STEP; ++j) {
            size_t o = base2 + (size_t)(t0 + j) * H2;
            float mu = bcast[0][j], rstd = bcast[1][j];
            float2 ov;
            ov.x = (h8[j].x - mu) * rstd * gm.x + bt.x + r8[j].x;
            ov.y = (h8[j].y - mu) * rstd * gm.y + bt.y + r8[j].y;
            if (write_out)
                __stcs(o2g + o, ov);
            if (write_split)
                __stcs(af2g + o, __floats2half2_rn(ov.x, ov.y));
        }
    }
}

// ============================================================================
extern "C" void kernel_launch(void* const* d_in, const int* in_sizes, int n_in,
                              void* d_out, int out_size)
{
    const float* x     = (const float*)d_in[0];
    const float* h0    = (const float*)d_in[1];
    const float* Wz    = (const float*)d_in[2];
    const float* bz    = (const float*)d_in[3];
    const float* Wh    = (const float*)d_in[4];
    const float* bh    = (const float*)d_in[5];
    const float* gamma = (const float*)d_in[6];
    const float* beta  = (const float*)d_in[7];

    float* out_cur = (float*)d_out;                       // (B, T, H)
    float* out_hid = out_cur + (size_t)MTOT * HID;        // (L, B, H)

    conv_w<<<(NLAYERS * HID * HID) / 256, 256>>>(Wz, Wh);
    conv_x<<<(MTOT * HID / 2) / 256, 256>>>(x);

    for (int i = 0; i < NLAYERS; ++i) {
        gates_gemm<<<dim3(8, MTOT / BM), 256, SMEM_BYTES>>>(
            i, bz + i * HID, bh + i * HID);
        scan_summary<<<BATCH * NC, 128>>>();
        scanB<<<64, 256>>>(h0 + (size_t)i * BATCH * HID,
                           out_hid + (size_t)i * BATCH * HID);
        int last = (i == NLAYERS - 1);
        scan_ln<<<BATCH * LNC, 256>>>(
            x,                                  // fp32 resid (layer 0 only)
            gamma + i * HID, beta + i * HID,
            out_cur,
            /*resid_is_fp16=*/(i > 0) ? 1 : 0,
            /*write_out=*/last,
            /*write_split=*/last ? 0 : 1);
    }
}

// round 15
// speedup vs baseline: 1.0689x; 1.0689x over previous
#include <cuda_runtime.h>
#include <cuda_bf16.h>
#include <cuda_fp16.h>
#include <cstdint>

#define NLAYERS 4
#define HID 512
#define BATCH 32
#define SEQ 2048
#define MTOT (BATCH*SEQ)          // 65536
#define NC 64                     // scan chunks
#define TC (SEQ/NC)               // 32 steps per chunk
#define H4 (HID/4)                // 128 channel-quads per row

// ---------------- GEMM tiling ----------------
#define BM 128
#define BN 128
#define BK 32
#define LDA 40                    // BK + 8 pad (row = 80B)
#define LDB 136                   // BN + 8 pad (row = 272B)
#define STAGE_EL (BM*LDA + BK*LDB)                // 9472 fp16
#define SMEM_BYTES (2*STAGE_EL*2)                 // 37888 bytes

// ---------------- scratch ----------------
__device__ __half g_ah[(size_t)MTOT * HID];       // a = sigmoid(-k)   (fp16)
__device__ __half g_gp[(size_t)MTOT * HID];       // gp = g(p)         (fp16)
__device__ __half g_Af[(size_t)MTOT * HID];       // activations / residual (fp16)
__device__ __half g_Wf[(size_t)NLAYERS * 2 * HID * HID];  // weights (fp16)
__device__ float g_cA[BATCH * NC * HID];
__device__ float g_cB[BATCH * NC * HID];
__device__ float g_hin[BATCH * NC * HID];

// ---------------- helpers ----------------
__device__ __forceinline__ uint32_t saddr(const void* p) {
    return (uint32_t)__cvta_generic_to_shared(p);
}
__device__ __forceinline__ void cpasync16(void* smem, const void* g) {
    asm volatile("cp.async.cg.shared.global [%0], [%1], 16;"
                 :: "r"(saddr(smem)), "l"(g));
}
__device__ __forceinline__ void cp_commit() {
    asm volatile("cp.async.commit_group;");
}
__device__ __forceinline__ void cp_wait0() {
    asm volatile("cp.async.wait_group 0;");
}
__device__ __forceinline__ void ldm_x4(uint32_t* r, uint32_t a) {
    asm volatile("ldmatrix.sync.aligned.m8n8.x4.shared.b16 {%0,%1,%2,%3}, [%4];"
                 : "=r"(r[0]), "=r"(r[1]), "=r"(r[2]), "=r"(r[3]) : "r"(a));
}
__device__ __forceinline__ void ldm_x2t(uint32_t* r, uint32_t a) {
    asm volatile("ldmatrix.sync.aligned.m8n8.x2.trans.shared.b16 {%0,%1}, [%2];"
                 : "=r"(r[0]), "=r"(r[1]) : "r"(a));
}
__device__ __forceinline__ void mma16816(float* c, const uint32_t* a, const uint32_t* b) {
    asm volatile(
        "mma.sync.aligned.m16n8k16.row.col.f32.f16.f16.f32 "
        "{%0,%1,%2,%3}, {%4,%5,%6,%7}, {%8,%9}, {%0,%1,%2,%3};"
        : "+f"(c[0]), "+f"(c[1]), "+f"(c[2]), "+f"(c[3])
        : "r"(a[0]), "r"(a[1]), "r"(a[2]), "r"(a[3]), "r"(b[0]), "r"(b[1]));
}
__device__ __forceinline__ float sig_neg(float v) {     // sigmoid(-v)
    return __fdividef(1.f, 1.f + __expf(v));
}
__device__ __forceinline__ float gfun(float v) {        // minGRU g()
    return (v >= 0.f) ? (v + 0.5f) : __fdividef(1.f, 1.f + __expf(-v));
}
__device__ __forceinline__ float4 half4_to_float4(uint2 v) {
    float2 lo = __half22float2(*(__half2*)&v.x);
    float2 hi = __half22float2(*(__half2*)&v.y);
    return make_float4(lo.x, lo.y, hi.x, hi.y);
}
__device__ __forceinline__ void unpack8(uint4 v, float* d) {
    float2 p;
    p = __half22float2(*(__half2*)&v.x); d[0] = p.x; d[1] = p.y;
    p = __half22float2(*(__half2*)&v.y); d[2] = p.x; d[3] = p.y;
    p = __half22float2(*(__half2*)&v.z); d[4] = p.x; d[5] = p.y;
    p = __half22float2(*(__half2*)&v.w); d[6] = p.x; d[7] = p.y;
}
__device__ __forceinline__ uint4 pack8(const float* s) {
    uint4 v;
    *(__half2*)&v.x = __floats2half2_rn(s[0], s[1]);
    *(__half2*)&v.y = __floats2half2_rn(s[2], s[3]);
    *(__half2*)&v.z = __floats2half2_rn(s[4], s[5]);
    *(__half2*)&v.w = __floats2half2_rn(s[6], s[7]);
    return v;
}

// ============================================================================
// One-shot conversion kernels
// ============================================================================
__global__ void __launch_bounds__(256) conv_w(const float* __restrict__ Wz,
                                              const float* __restrict__ Wh) {
    size_t i = (size_t)blockIdx.x * 256 + threadIdx.x;    // over 4*512*512
    size_t l = i >> 18, r = i & ((1u << 18) - 1);
    g_Wf[((l * 2 + 0) << 18) + r] = __float2half_rn(Wz[i]);
    g_Wf[((l * 2 + 1) << 18) + r] = __float2half_rn(Wh[i]);
}

__global__ void __launch_bounds__(256) conv_x(const float* __restrict__ x) {
    size_t i = (size_t)blockIdx.x * 256 + threadIdx.x;    // over MTOT*HID/2
    float2 v = ((const float2*)x)[i];
    ((__half2*)g_Af)[i] = __floats2half2_rn(v.x, v.y);
}

// ============================================================================
// Fused dual GEMM, fp16 operands, fp32 accumulate.
// Epilogue applies the gate activation: zsel=0 stores a=sigmoid(-(k)),
// zsel=1 stores gp=g(p).  grid = (8, MTOT/128).
// ============================================================================
__global__ void __launch_bounds__(256, 2) gates_gemm(
    int layer, const float* __restrict__ bz, const float* __restrict__ bh)
{
    extern __shared__ __align__(16) char smem_raw[];
    __half* s = (__half*)smem_raw;

    const int tid  = threadIdx.x;
    const int lane = tid & 31;
    const int warp = tid >> 5;
    const int wm   = warp >> 2;
    const int wn   = warp & 3;
    const int zsel = blockIdx.x >> 2;
    const int colBase = (blockIdx.x & 3) * BN;
    const size_t rowBase = (size_t)blockIdx.y * BM;

    const __half* W_   = g_Wf + (((size_t)layer * 2 + zsel) << 18);
    const float* bias  = zsel ? bh : bz;
    __half*      Out   = zsel ? g_gp : g_ah;

    auto issue = [&](int kt, int st) {
        __half* sb = s + st * STAGE_EL;
        {
#pragma unroll
            for (int j = 0; j < 2; ++j) {
                int i = tid + 256 * j;
                int row = i >> 2, ch = i & 3;
                const __half* gsrc = g_Af + (rowBase + row) * HID + kt * BK + ch * 8;
                cpasync16(sb + row * LDA + ch * 8, gsrc);
            }
        }
        {
#pragma unroll
            for (int j = 0; j < 2; ++j) {
                int i = tid + 256 * j;
                int row = i >> 4, ch = i & 15;
                const __half* gsrc = W_ + (size_t)(kt * BK + row) * HID + colBase + ch * 8;
                cpasync16(sb + BM * LDA + row * LDB + ch * 8, gsrc);
            }
        }
        cp_commit();
    };

    float acc[4][4][4];
#pragma unroll
    for (int mt = 0; mt < 4; ++mt)
#pragma unroll
        for (int nt = 0; nt < 4; ++nt)
#pragma unroll
            for (int r = 0; r < 4; ++r) acc[mt][nt][r] = 0.f;

    auto comp = [&](int st) {
        const __half* sA = s + st * STAGE_EL;
        const __half* sB = sA + BM * LDA;
#pragma unroll
        for (int ks = 0; ks < 2; ++ks) {
            uint32_t B[4][2];
#pragma unroll
            for (int nt = 0; nt < 4; ++nt) {
                int br = ks * 16 + (lane & 15);
                int bc = wn * 32 + nt * 8;
                ldm_x2t(B[nt], saddr(sB + br * LDB + bc));
            }
#pragma unroll
            for (int mt = 0; mt < 4; ++mt) {
                uint32_t A[4];
                int ar = wm * 64 + mt * 16 + (lane & 15);
                int ac = ks * 16 + ((lane >> 4) << 3);
                ldm_x4(A, saddr(sA + ar * LDA + ac));
#pragma unroll
                for (int nt = 0; nt < 4; ++nt)
                    mma16816(acc[mt][nt], A, B[nt]);
            }
        }
    };

    issue(0, 0);
    const int KI = HID / BK;    // 16
    for (int kt = 0; kt < KI; ++kt) {
        int st = kt & 1;
        cp_wait0();
        __syncthreads();
        if (kt + 1 < KI) issue(kt + 1, st ^ 1);
        comp(st);
    }

#pragma unroll
    for (int mt = 0; mt < 4; ++mt) {
        size_t r0 = rowBase + wm * 64 + mt * 16 + (lane >> 2);
#pragma unroll
        for (int nt = 0; nt < 4; ++nt) {
            int cb = colBase + wn * 32 + nt * 8 + ((lane & 3) << 1);
            float2 bs = *(const float2*)(bias + cb);
            float v0 = acc[mt][nt][0] + bs.x, v1 = acc[mt][nt][1] + bs.y;
            float v2 = acc[mt][nt][2] + bs.x, v3 = acc[mt][nt][3] + bs.y;
            if (zsel == 0) {
                v0 = sig_neg(v0); v1 = sig_neg(v1);
                v2 = sig_neg(v2); v3 = sig_neg(v3);
            } else {
                v0 = gfun(v0); v1 = gfun(v1);
                v2 = gfun(v2); v3 = gfun(v3);
            }
            *(__half2*)(Out + r0 * HID + cb)       = __floats2half2_rn(v0, v1);
            *(__half2*)(Out + (r0 + 8) * HID + cb) = __floats2half2_rn(v2, v3);
        }
    }
}

// ============================================================================
// Scan summary pass: chunk (P, S); pure FMA (activations precomputed).
// grid = BATCH*NC = 2048 blocks x 128 threads, 4 channels/thread, TC=32 steps.
// ============================================================================
__global__ void __launch_bounds__(128) scan_summary() {
    int b     = blockIdx.x >> 6;                  // NC = 64
    int chunk = blockIdx.x & (NC - 1);
    int c4    = threadIdx.x;                      // quad index 0..127
    size_t base = ((size_t)(b * SEQ + chunk * TC)) * H4 + c4;

    const uint2* a4g = (const uint2*)g_ah;
    const uint2* g4g = (const uint2*)g_gp;

    float S[4] = {0.f, 0.f, 0.f, 0.f};
    float P[4] = {1.f, 1.f, 1.f, 1.f};
#pragma unroll 8
    for (int t = 0; t < TC; ++t) {
        size_t o = base + (size_t)t * H4;
        float4 a = half4_to_float4(__ldcs(a4g + o));
        float4 g = half4_to_float4(__ldcs(g4g + o));
        S[0] = fmaf(a.x, S[0] - g.x, g.x);  P[0] *= a.x;
        S[1] = fmaf(a.y, S[1] - g.y, g.y);  P[1] *= a.y;
        S[2] = fmaf(a.z, S[2] - g.z, g.z);  P[2] *= a.z;
        S[3] = fmaf(a.w, S[3] - g.w, g.w);  P[3] *= a.w;
    }
    ((float4*)g_cA)[(b * NC + chunk) * H4 + c4] = make_float4(P[0], P[1], P[2], P[3]);
    ((float4*)g_cB)[(b * NC + chunk) * H4 + c4] = make_float4(S[0], S[1], S[2], S[3]);
}

// ============================================================================
// Chain chunk summaries; emit per-chunk h_in and final hiddens.
// ============================================================================
__global__ void __launch_bounds__(256) scanB(const float* __restrict__ h0l,
                                             float* __restrict__ hid_out) {
    int idx = blockIdx.x * 256 + threadIdx.x;   // 16384
    int b = idx >> 9, c = idx & 511;
    float x0 = h0l[b * HID + c];
    float h = (x0 >= 0.f) ? (x0 + 0.5f)
                          : __fdividef(1.f, 1.f + __expf(-x0));
#pragma unroll
    for (int j = 0; j < NC; ++j) {
        g_hin[(b * NC + j) * HID + c] = h;
        h = fmaf(g_cA[(b * NC + j) * HID + c], h, g_cB[(b * NC + j) * HID + c]);
    }
    hid_out[b * HID + c] = h;
}

// ============================================================================
// Warp-autonomous fused scan + LayerNorm + residual. NO block barriers.
// One WARP per (b, chunk): lane owns 16 channels (512 = 32*16); LN reduction
// is 15 local adds + a 5-level shfl butterfly. Depth-2 load pipeline.
// RF16: residual from fp16 g_Af (in place; each element read before rewrite).
// WOUT: write fp32 d_out.  WSPLIT: write fp16 g_Af for the next layer.
// ============================================================================
template<bool RF16, bool WOUT, bool WSPLIT>
__global__ void __launch_bounds__(128) scan_ln_t(const float* __restrict__ residf,
                                                 const float* __restrict__ gamma,
                                                 const float* __restrict__ beta,
                                                 float* __restrict__ outp) {
    int wid  = (blockIdx.x << 2) + (threadIdx.x >> 5);   // global warp 0..2047
    int lane = threadIdx.x & 31;
    int b = wid >> 6, chunk = wid & (NC - 1);
    int c0 = lane << 4;                                  // 16 channels per lane
    size_t base = ((size_t)b * SEQ + (size_t)chunk * TC) * HID + c0;

    float h[16], gm[16], bt[16];
#pragma unroll
    for (int i = 0; i < 4; ++i) {
        float4 v = *((const float4*)(g_hin + (size_t)(b * NC + chunk) * HID + c0) + i);
        h[4*i] = v.x; h[4*i+1] = v.y; h[4*i+2] = v.z; h[4*i+3] = v.w;
        float4 g = __ldg((const float4*)(gamma + c0) + i);
        gm[4*i] = g.x; gm[4*i+1] = g.y; gm[4*i+2] = g.z; gm[4*i+3] = g.w;
        float4 bb = __ldg((const float4*)(beta + c0) + i);
        bt[4*i] = bb.x; bt[4*i+1] = bb.y; bt[4*i+2] = bb.z; bt[4*i+3] = bb.w;
    }

    uint4 aS[2][2], gS[2][2], rh[2][2];
    float4 rf[2][4];

    auto loadt = [&](int t, int st) {
        size_t o = base + (size_t)t * HID;
        aS[st][0] = __ldcs((const uint4*)(g_ah + o));
        aS[st][1] = __ldcs((const uint4*)(g_ah + o + 8));
        gS[st][0] = __ldcs((const uint4*)(g_gp + o));
        gS[st][1] = __ldcs((const uint4*)(g_gp + o + 8));
        if (RF16) {
            rh[st][0] = __ldcs((const uint4*)(g_Af + o));
            rh[st][1] = __ldcs((const uint4*)(g_Af + o + 8));
        } else {
#pragma unroll
            for (int i = 0; i < 4; ++i)
                rf[st][i] = __ldcs((const float4*)(residf + o) + i);
        }
    };
    loadt(0, 0);
    loadt(1, 1);

#pragma unroll 2
    for (int t = 0; t < TC; ++t) {
        const int st = t & 1;
        float a[16], gp[16], r[16];
        unpack8(aS[st][0], a);  unpack8(aS[st][1], a + 8);
        unpack8(gS[st][0], gp); unpack8(gS[st][1], gp + 8);
        if (RF16) {
            unpack8(rh[st][0], r); unpack8(rh[st][1], r + 8);
        } else {
#pragma unroll
            for (int i = 0; i < 4; ++i) {
                r[4*i] = rf[st][i].x; r[4*i+1] = rf[st][i].y;
                r[4*i+2] = rf[st][i].z; r[4*i+3] = rf[st][i].w;
            }
        }
        if (t + 2 < TC) loadt(t + 2, st);       // staging regs just freed

        float sm = 0.f, q = 0.f;
#pragma unroll
        for (int i = 0; i < 16; ++i) {
            h[i] = fmaf(a[i], h[i] - gp[i], gp[i]);
            sm += h[i];
            q = fmaf(h[i], h[i], q);
        }
#pragma unroll
        for (int off = 16; off; off >>= 1) {
            sm += __shfl_xor_sync(0xffffffffu, sm, off);
            q  += __shfl_xor_sync(0xffffffffu, q,  off);
        }
        float mu   = sm * (1.f / HID);
        float rstd = rsqrtf(fmaf(q, 1.f / HID, -mu * mu) + 1e-5f);

        size_t o = base + (size_t)t * HID;
        float ov[16];
#pragma unroll
        for (int i = 0; i < 16; ++i)
            ov[i] = (h[i] - mu) * rstd * gm[i] + bt[i] + r[i];
        if (WOUT) {
#pragma unroll
            for (int i = 0; i < 4; ++i)
                __stcs((float4*)(outp + o) + i,
                       make_float4(ov[4*i], ov[4*i+1], ov[4*i+2], ov[4*i+3]));
        }
        if (WSPLIT) {
            __stcs((uint4*)(g_Af + o),     pack8(ov));
            __stcs((uint4*)(g_Af + o + 8), pack8(ov + 8));
        }
    }
}

// ============================================================================
extern "C" void kernel_launch(void* const* d_in, const int* in_sizes, int n_in,
                              void* d_out, int out_size)
{
    const float* x     = (const float*)d_in[0];
    const float* h0    = (const float*)d_in[1];
    const float* Wz    = (const float*)d_in[2];
    const float* bz    = (const float*)d_in[3];
    const float* Wh    = (const float*)d_in[4];
    const float* bh    = (const float*)d_in[5];
    const float* gamma = (const float*)d_in[6];
    const float* beta  = (const float*)d_in[7];

    float* out_cur = (float*)d_out;                       // (B, T, H)
    float* out_hid = out_cur + (size_t)MTOT * HID;        // (L, B, H)

    conv_w<<<(NLAYERS * HID * HID) / 256, 256>>>(Wz, Wh);
    conv_x<<<(MTOT * HID / 2) / 256, 256>>>(x);

    const int LN_GRID = BATCH * NC / 4;   // 512 blocks of 4 warps

    for (int i = 0; i < NLAYERS; ++i) {
        gates_gemm<<<dim3(8, MTOT / BM), 256, SMEM_BYTES>>>(
            i, bz + i * HID, bh + i * HID);
        scan_summary<<<BATCH * NC, 128>>>();
        scanB<<<64, 256>>>(h0 + (size_t)i * BATCH * HID,
                           out_hid + (size_t)i * BATCH * HID);
        if (i == 0)
            scan_ln_t<false, false, true><<<LN_GRID, 128>>>(
                x, gamma + i * HID, beta + i * HID, out_cur);
        else if (i < NLAYERS - 1)
            scan_ln_t<true, false, true><<<LN_GRID, 128>>>(
                x, gamma + i * HID, beta + i * HID, out_cur);
        else
            scan_ln_t<true, true, false><<<LN_GRID, 128>>>(
                x, gamma + i * HID, beta + i * HID, out_cur);
    }
}

// round 16
// speedup vs baseline: 1.1606x; 1.0857x over previous
#include <cuda_runtime.h>
#include <cuda_bf16.h>
#include <cuda_fp16.h>
#include <cstdint>

#define NLAYERS 4
#define HID 512
#define BATCH 32
#define SEQ 2048
#define MTOT (BATCH*SEQ)          // 65536
#define NC 64                     // scan chunks
#define TC (SEQ/NC)               // 32 steps per chunk
#define H4 (HID/4)                // 128 channel-quads per row

// ---------------- GEMM tiling ----------------
#define BM 128
#define BN 128
#define BK 32
#define LDA 40                    // BK + 8 pad (row = 80B)
#define LDB 136                   // BN + 8 pad (row = 272B)
#define STAGE_EL (BM*LDA + BK*LDB)                // 9472 fp16
#define NSTAGE 3
#define SMEM_BYTES (NSTAGE*STAGE_EL*2)            // 56832 bytes

// ---------------- scratch ----------------
__device__ __half g_ah[(size_t)MTOT * HID];       // a = sigmoid(-k)   (fp16)
__device__ __half g_gp[(size_t)MTOT * HID];       // gp = g(p)         (fp16)
__device__ __half g_Af[(size_t)MTOT * HID];       // activations / residual (fp16)
__device__ __half g_Wf[(size_t)NLAYERS * 2 * HID * HID];  // weights (fp16)
__device__ float g_cA[BATCH * NC * HID];
__device__ float g_cB[BATCH * NC * HID];
__device__ float g_hin[BATCH * NC * HID];

// ---------------- helpers ----------------
__device__ __forceinline__ uint32_t saddr(const void* p) {
    return (uint32_t)__cvta_generic_to_shared(p);
}
__device__ __forceinline__ void cpasync16(void* smem, const void* g) {
    asm volatile("cp.async.cg.shared.global [%0], [%1], 16;"
                 :: "r"(saddr(smem)), "l"(g));
}
__device__ __forceinline__ void cp_commit() {
    asm volatile("cp.async.commit_group;");
}
template <int N>
__device__ __forceinline__ void cp_wait() {
    asm volatile("cp.async.wait_group %0;" :: "n"(N));
}
__device__ __forceinline__ void ldm_x4(uint32_t* r, uint32_t a) {
    asm volatile("ldmatrix.sync.aligned.m8n8.x4.shared.b16 {%0,%1,%2,%3}, [%4];"
                 : "=r"(r[0]), "=r"(r[1]), "=r"(r[2]), "=r"(r[3]) : "r"(a));
}
__device__ __forceinline__ void ldm_x2t(uint32_t* r, uint32_t a) {
    asm volatile("ldmatrix.sync.aligned.m8n8.x2.trans.shared.b16 {%0,%1}, [%2];"
                 : "=r"(r[0]), "=r"(r[1]) : "r"(a));
}
__device__ __forceinline__ void mma16816(float* c, const uint32_t* a, const uint32_t* b) {
    asm volatile(
        "mma.sync.aligned.m16n8k16.row.col.f32.f16.f16.f32 "
        "{%0,%1,%2,%3}, {%4,%5,%6,%7}, {%8,%9}, {%0,%1,%2,%3};"
        : "+f"(c[0]), "+f"(c[1]), "+f"(c[2]), "+f"(c[3])
        : "r"(a[0]), "r"(a[1]), "r"(a[2]), "r"(a[3]), "r"(b[0]), "r"(b[1]));
}
__device__ __forceinline__ float sig_neg(float v) {     // sigmoid(-v)
    return __fdividef(1.f, 1.f + __expf(v));
}
__device__ __forceinline__ float gfun(float v) {        // minGRU g()
    return (v >= 0.f) ? (v + 0.5f) : __fdividef(1.f, 1.f + __expf(-v));
}
__device__ __forceinline__ float4 half4_to_float4(uint2 v) {
    float2 lo = __half22float2(*(__half2*)&v.x);
    float2 hi = __half22float2(*(__half2*)&v.y);
    return make_float4(lo.x, lo.y, hi.x, hi.y);
}
__device__ __forceinline__ void unpack8(uint4 v, float* d) {
    float2 p;
    p = __half22float2(*(__half2*)&v.x); d[0] = p.x; d[1] = p.y;
    p = __half22float2(*(__half2*)&v.y); d[2] = p.x; d[3] = p.y;
    p = __half22float2(*(__half2*)&v.z); d[4] = p.x; d[5] = p.y;
    p = __half22float2(*(__half2*)&v.w); d[6] = p.x; d[7] = p.y;
}
__device__ __forceinline__ uint4 pack8(const float* s) {
    uint4 v;
    *(__half2*)&v.x = __floats2half2_rn(s[0], s[1]);
    *(__half2*)&v.y = __floats2half2_rn(s[2], s[3]);
    *(__half2*)&v.z = __floats2half2_rn(s[4], s[5]);
    *(__half2*)&v.w = __floats2half2_rn(s[6], s[7]);
    return v;
}

// ============================================================================
// One-shot conversion kernels (+ no-op used to align the ncu capture window)
// ============================================================================
__global__ void noop_kernel() {}

__global__ void __launch_bounds__(256) conv_w(const float* __restrict__ Wz,
                                              const float* __restrict__ Wh) {
    size_t i = (size_t)blockIdx.x * 256 + threadIdx.x;    // over 4*512*512
    size_t l = i >> 18, r = i & ((1u << 18) - 1);
    g_Wf[((l * 2 + 0) << 18) + r] = __float2half_rn(Wz[i]);
    g_Wf[((l * 2 + 1) << 18) + r] = __float2half_rn(Wh[i]);
}

__global__ void __launch_bounds__(256) conv_x(const float* __restrict__ x) {
    size_t i = (size_t)blockIdx.x * 256 + threadIdx.x;    // over MTOT*HID/2
    float2 v = ((const float2*)x)[i];
    ((__half2*)g_Af)[i] = __floats2half2_rn(v.x, v.y);
}

// ============================================================================
// Fused dual GEMM, fp16 operands, fp32 accumulate, 3-stage cp.async pipeline.
// Epilogue applies the gate activation: zsel=0 stores a=sigmoid(-(k)),
// zsel=1 stores gp=g(p).  grid = (8, MTOT/128).
// ============================================================================
__global__ void __launch_bounds__(256, 2) gates_gemm(
    int layer, const float* __restrict__ bz, const float* __restrict__ bh)
{
    extern __shared__ __align__(16) char smem_raw[];
    __half* s = (__half*)smem_raw;

    const int tid  = threadIdx.x;
    const int lane = tid & 31;
    const int warp = tid >> 5;
    const int wm   = warp >> 2;
    const int wn   = warp & 3;
    const int zsel = blockIdx.x >> 2;
    const int colBase = (blockIdx.x & 3) * BN;
    const size_t rowBase = (size_t)blockIdx.y * BM;

    const __half* W_   = g_Wf + (((size_t)layer * 2 + zsel) << 18);
    const float* bias  = zsel ? bh : bz;
    __half*      Out   = zsel ? g_gp : g_ah;

    auto issue = [&](int kt, int st) {
        __half* sb = s + st * STAGE_EL;
        {
#pragma unroll
            for (int j = 0; j < 2; ++j) {
                int i = tid + 256 * j;
                int row = i >> 2, ch = i & 3;
                const __half* gsrc = g_Af + (rowBase + row) * HID + kt * BK + ch * 8;
                cpasync16(sb + row * LDA + ch * 8, gsrc);
            }
        }
        {
#pragma unroll
            for (int j = 0; j < 2; ++j) {
                int i = tid + 256 * j;
                int row = i >> 4, ch = i & 15;
                const __half* gsrc = W_ + (size_t)(kt * BK + row) * HID + colBase + ch * 8;
                cpasync16(sb + BM * LDA + row * LDB + ch * 8, gsrc);
            }
        }
        cp_commit();
    };

    float acc[4][4][4];
#pragma unroll
    for (int mt = 0; mt < 4; ++mt)
#pragma unroll
        for (int nt = 0; nt < 4; ++nt)
#pragma unroll
            for (int r = 0; r < 4; ++r) acc[mt][nt][r] = 0.f;

    auto comp = [&](int st) {
        const __half* sA = s + st * STAGE_EL;
        const __half* sB = sA + BM * LDA;
#pragma unroll
        for (int ks = 0; ks < 2; ++ks) {
            uint32_t B[4][2];
#pragma unroll
            for (int nt = 0; nt < 4; ++nt) {
                int br = ks * 16 + (lane & 15);
                int bc = wn * 32 + nt * 8;
                ldm_x2t(B[nt], saddr(sB + br * LDB + bc));
            }
#pragma unroll
            for (int mt = 0; mt < 4; ++mt) {
                uint32_t A[4];
                int ar = wm * 64 + mt * 16 + (lane & 15);
                int ac = ks * 16 + ((lane >> 4) << 3);
                ldm_x4(A, saddr(sA + ar * LDA + ac));
#pragma unroll
                for (int nt = 0; nt < 4; ++nt)
                    mma16816(acc[mt][nt], A, B[nt]);
            }
        }
    };

    const int KI = HID / BK;    // 16
    issue(0, 0);
    issue(1, 1);
    for (int kt = 0; kt < KI; ++kt) {
        int st = kt % NSTAGE;
        if (kt == KI - 1) cp_wait<0>(); else cp_wait<1>();
        __syncthreads();
        if (kt + 2 < KI) issue(kt + 2, (kt + 2) % NSTAGE);
        comp(st);
    }

#pragma unroll
    for (int mt = 0; mt < 4; ++mt) {
        size_t r0 = rowBase + wm * 64 + mt * 16 + (lane >> 2);
#pragma unroll
        for (int nt = 0; nt < 4; ++nt) {
            int cb = colBase + wn * 32 + nt * 8 + ((lane & 3) << 1);
            float2 bs = *(const float2*)(bias + cb);
            float v0 = acc[mt][nt][0] + bs.x, v1 = acc[mt][nt][1] + bs.y;
            float v2 = acc[mt][nt][2] + bs.x, v3 = acc[mt][nt][3] + bs.y;
            if (zsel == 0) {
                v0 = sig_neg(v0); v1 = sig_neg(v1);
                v2 = sig_neg(v2); v3 = sig_neg(v3);
            } else {
                v0 = gfun(v0); v1 = gfun(v1);
                v2 = gfun(v2); v3 = gfun(v3);
            }
            *(__half2*)(Out + r0 * HID + cb)       = __floats2half2_rn(v0, v1);
            *(__half2*)(Out + (r0 + 8) * HID + cb) = __floats2half2_rn(v2, v3);
        }
    }
}

// ============================================================================
// Scan summary pass: chunk (P, S); pure FMA (activations precomputed).
// grid = BATCH*NC = 2048 blocks x 128 threads, 4 channels/thread, TC=32 steps.
// ============================================================================
__global__ void __launch_bounds__(128) scan_summary() {
    int b     = blockIdx.x >> 6;                  // NC = 64
    int chunk = blockIdx.x & (NC - 1);
    int c4    = threadIdx.x;                      // quad index 0..127
    size_t base = ((size_t)(b * SEQ + chunk * TC)) * H4 + c4;

    const uint2* a4g = (const uint2*)g_ah;
    const uint2* g4g = (const uint2*)g_gp;

    float S[4] = {0.f, 0.f, 0.f, 0.f};
    float P[4] = {1.f, 1.f, 1.f, 1.f};
#pragma unroll 8
    for (int t = 0; t < TC; ++t) {
        size_t o = base + (size_t)t * H4;
        float4 a = half4_to_float4(__ldcs(a4g + o));
        float4 g = half4_to_float4(__ldcs(g4g + o));
        S[0] = fmaf(a.x, S[0] - g.x, g.x);  P[0] *= a.x;
        S[1] = fmaf(a.y, S[1] - g.y, g.y);  P[1] *= a.y;
        S[2] = fmaf(a.z, S[2] - g.z, g.z);  P[2] *= a.z;
        S[3] = fmaf(a.w, S[3] - g.w, g.w);  P[3] *= a.w;
    }
    ((float4*)g_cA)[(b * NC + chunk) * H4 + c4] = make_float4(P[0], P[1], P[2], P[3]);
    ((float4*)g_cB)[(b * NC + chunk) * H4 + c4] = make_float4(S[0], S[1], S[2], S[3]);
}

// ============================================================================
// Chain chunk summaries; emit per-chunk h_in and final hiddens.
// ============================================================================
__global__ void __launch_bounds__(256) scanB(const float* __restrict__ h0l,
                                             float* __restrict__ hid_out) {
    int idx = blockIdx.x * 256 + threadIdx.x;   // 16384
    int b = idx >> 9, c = idx & 511;
    float x0 = h0l[b * HID + c];
    float h = (x0 >= 0.f) ? (x0 + 0.5f)
                          : __fdividef(1.f, 1.f + __expf(-x0));
#pragma unroll
    for (int j = 0; j < NC; ++j) {
        g_hin[(b * NC + j) * HID + c] = h;
        h = fmaf(g_cA[(b * NC + j) * HID + c], h, g_cB[(b * NC + j) * HID + c]);
    }
    hid_out[b * HID + c] = h;
}

// ============================================================================
// Warp-autonomous fused scan + LayerNorm + residual. NO block barriers.
// One WARP per (b, chunk): lane owns 16 channels (512 = 32*16); LN reduction
// is 15 local adds + a 5-level shfl butterfly. Depth-2 load pipeline.
// RF16: residual from fp16 g_Af (in place; each element read before rewrite).
// WOUT: write fp32 d_out.  WSPLIT: write fp16 g_Af for the next layer.
// ============================================================================
template<bool RF16, bool WOUT, bool WSPLIT>
__global__ void __launch_bounds__(128) scan_ln_t(const float* __restrict__ residf,
                                                 const float* __restrict__ gamma,
                                                 const float* __restrict__ beta,
                                                 float* __restrict__ outp) {
    int wid  = (blockIdx.x << 2) + (threadIdx.x >> 5);   // global warp 0..2047
    int lane = threadIdx.x & 31;
    int b = wid >> 6, chunk = wid & (NC - 1);
    int c0 = lane << 4;                                  // 16 channels per lane
    size_t base = ((size_t)b * SEQ + (size_t)chunk * TC) * HID + c0;

    float h[16], gm[16], bt[16];
#pragma unroll
    for (int i = 0; i < 4; ++i) {
        float4 v = *((const float4*)(g_hin + (size_t)(b * NC + chunk) * HID + c0) + i);
        h[4*i] = v.x; h[4*i+1] = v.y; h[4*i+2] = v.z; h[4*i+3] = v.w;
        float4 g = __ldg((const float4*)(gamma + c0) + i);
        gm[4*i] = g.x; gm[4*i+1] = g.y; gm[4*i+2] = g.z; gm[4*i+3] = g.w;
        float4 bb = __ldg((const float4*)(beta + c0) + i);
        bt[4*i] = bb.x; bt[4*i+1] = bb.y; bt[4*i+2] = bb.z; bt[4*i+3] = bb.w;
    }

    uint4 aS[2][2], gS[2][2], rh[2][2];
    float4 rf[2][4];

    auto loadt = [&](int t, int st) {
        size_t o = base + (size_t)t * HID;
        aS[st][0] = __ldcs((const uint4*)(g_ah + o));
        aS[st][1] = __ldcs((const uint4*)(g_ah + o + 8));
        gS[st][0] = __ldcs((const uint4*)(g_gp + o));
        gS[st][1] = __ldcs((const uint4*)(g_gp + o + 8));
        if (RF16) {
            rh[st][0] = __ldcs((const uint4*)(g_Af + o));
            rh[st][1] = __ldcs((const uint4*)(g_Af + o + 8));
        } else {
#pragma unroll
            for (int i = 0; i < 4; ++i)
                rf[st][i] = __ldcs((const float4*)(residf + o) + i);
        }
    };
    loadt(0, 0);
    loadt(1, 1);

#pragma unroll 2
    for (int t = 0; t < TC; ++t) {
        const int st = t & 1;
        float a[16], gp[16], r[16];
        unpack8(aS[st][0], a);  unpack8(aS[st][1], a + 8);
        unpack8(gS[st][0], gp); unpack8(gS[st][1], gp + 8);
        if (RF16) {
            unpack8(rh[st][0], r); unpack8(rh[st][1], r + 8);
        } else {
#pragma unroll
            for (int i = 0; i < 4; ++i) {
                r[4*i] = rf[st][i].x; r[4*i+1] = rf[st][i].y;
                r[4*i+2] = rf[st][i].z; r[4*i+3] = rf[st][i].w;
            }
        }
        if (t + 2 < TC) loadt(t + 2, st);       // staging regs just freed

        float sm = 0.f, q = 0.f;
#pragma unroll
        for (int i = 0; i < 16; ++i) {
            h[i] = fmaf(a[i], h[i] - gp[i], gp[i]);
            sm += h[i];
            q = fmaf(h[i], h[i], q);
        }
#pragma unroll
        for (int off = 16; off; off >>= 1) {
            sm += __shfl_xor_sync(0xffffffffu, sm, off);
            q  += __shfl_xor_sync(0xffffffffu, q,  off);
        }
        float mu   = sm * (1.f / HID);
        float rstd = rsqrtf(fmaf(q, 1.f / HID, -mu * mu) + 1e-5f);

        size_t o = base + (size_t)t * HID;
        float ov[16];
#pragma unroll
        for (int i = 0; i < 16; ++i)
            ov[i] = (h[i] - mu) * rstd * gm[i] + bt[i] + r[i];
        if (WOUT) {
#pragma unroll
            for (int i = 0; i < 4; ++i)
                __stcs((float4*)(outp + o) + i,
                       make_float4(ov[4*i], ov[4*i+1], ov[4*i+2], ov[4*i+3]));
        }
        if (WSPLIT) {
            __stcs((uint4*)(g_Af + o),     pack8(ov));
            __stcs((uint4*)(g_Af + o + 8), pack8(ov + 8));
        }
    }
}

// ============================================================================
extern "C" void kernel_launch(void* const* d_in, const int* in_sizes, int n_in,
                              void* d_out, int out_size)
{
    const float* x     = (const float*)d_in[0];
    const float* h0    = (const float*)d_in[1];
    const float* Wz    = (const float*)d_in[2];
    const float* bz    = (const float*)d_in[3];
    const float* Wh    = (const float*)d_in[4];
    const float* bh    = (const float*)d_in[5];
    const float* gamma = (const float*)d_in[6];
    const float* beta  = (const float*)d_in[7];

    float* out_cur = (float*)d_out;                       // (B, T, H)
    float* out_hid = out_cur + (size_t)MTOT * HID;        // (L, B, H)

    cudaFuncSetAttribute(gates_gemm,
                         cudaFuncAttributeMaxDynamicSharedMemorySize, SMEM_BYTES);

    conv_w<<<(NLAYERS * HID * HID) / 256, 256>>>(Wz, Wh);
    conv_x<<<(MTOT * HID / 2) / 256, 256>>>(x);
    noop_kernel<<<1, 32>>>();    // shifts the ncu capture window onto gates_gemm

    const int LN_GRID = BATCH * NC / 4;   // 512 blocks of 4 warps

    for (int i = 0; i < NLAYERS; ++i) {
        gates_gemm<<<dim3(8, MTOT / BM), 256, SMEM_BYTES>>>(
            i, bz + i * HID, bh + i * HID);
        scan_summary<<<BATCH * NC, 128>>>();
        scanB<<<64, 256>>>(h0 + (size_t)i * BATCH * HID,
                           out_hid + (size_t)i * BATCH * HID);
        if (i == 0)
            scan_ln_t<false, false, true><<<LN_GRID, 128>>>(
                x, gamma + i * HID, beta + i * HID, out_cur);
        else if (i < NLAYERS - 1)
            scan_ln_t<true, false, true><<<LN_GRID, 128>>>(
                x, gamma + i * HID, beta + i * HID, out_cur);
        else
            scan_ln_t<true, true, false><<<LN_GRID, 128>>>(
                x, gamma + i * HID, beta + i * HID, out_cur);
    }
}